// round 5
// baseline (speedup 1.0000x reference)
#include <cuda_runtime.h>
#include <cuda_bf16.h>
#include <cstdint>
#include <cstddef>

// Problem constants: B=16, H=8, L=512, D=64
#define BH   128
#define LEN  512
#define DIM  64
#define TI   32          // q-rows per CTA
#define NT   256         // threads (8 warps, 2x4 warp grid)
#define NJT  8           // 512/64 j-tiles
#define PB   72          // bf16 smem pitch
#define PEF  516         // f32 smem pitch for E
#define NELEM (BH*LEN*DIM)   // 4194304 per tensor

// smem byte offsets
#define OFF_KH 0                 // 64 x 72 bf16 = 9216 B
#define OFF_KL 9216
#define OFF_VH 18432
#define OFF_VL 27648
#define OFF_QH 36864             // 32 x 72 bf16 = 4608 B
#define OFF_QL 41472
#define OFF_EF 46080             // 32 x 516 f32 = 66048 B
#define OFF_MC 112128            // 512 f32
#define OFF_RS 114176            // 32 x 4 f32 partial row sums
#define OFF_RI 114688            // 32 f32 reciprocal row sums
#define SMEM_BYTES 114816
// O-reduction buffer reuses dead K/V region after the j-loop
#define OBP 66                   // f32 pitch for Obuf rows (bank-spread)

// pre-split bf16 hi/lo scratch (written by prologue kernel)
__device__ __nv_bfloat16 g_qh[NELEM];
__device__ __nv_bfloat16 g_ql[NELEM];
__device__ __nv_bfloat16 g_kh[NELEM];
__device__ __nv_bfloat16 g_kl[NELEM];
__device__ __nv_bfloat16 g_vh[NELEM];
__device__ __nv_bfloat16 g_vl[NELEM];

__device__ __forceinline__ uint32_t smem_u32(const void* p) {
    return (uint32_t)__cvta_generic_to_shared(p);
}
__device__ __forceinline__ void ldsm4(uint32_t* r, uint32_t a) {
    asm volatile("ldmatrix.sync.aligned.m8n8.x4.shared.b16 {%0,%1,%2,%3}, [%4];"
                 : "=r"(r[0]), "=r"(r[1]), "=r"(r[2]), "=r"(r[3]) : "r"(a));
}
__device__ __forceinline__ void ldsm4t(uint32_t* r, uint32_t a) {
    asm volatile("ldmatrix.sync.aligned.m8n8.x4.trans.shared.b16 {%0,%1,%2,%3}, [%4];"
                 : "=r"(r[0]), "=r"(r[1]), "=r"(r[2]), "=r"(r[3]) : "r"(a));
}
__device__ __forceinline__ void mma_bf16(float* c, const uint32_t* a, uint32_t b0, uint32_t b1) {
    asm volatile("mma.sync.aligned.m16n8k16.row.col.f32.bf16.bf16.f32 "
                 "{%0,%1,%2,%3}, {%4,%5,%6,%7}, {%8,%9}, {%0,%1,%2,%3};"
                 : "+f"(c[0]), "+f"(c[1]), "+f"(c[2]), "+f"(c[3])
                 : "r"(a[0]), "r"(a[1]), "r"(a[2]), "r"(a[3]), "r"(b0), "r"(b1));
}
__device__ __forceinline__ void split2(float x0, float x1, uint32_t& h, uint32_t& l) {
    __nv_bfloat16 h0 = __float2bfloat16(x0);
    __nv_bfloat16 h1 = __float2bfloat16(x1);
    __nv_bfloat16 l0 = __float2bfloat16(x0 - __bfloat162float(h0));
    __nv_bfloat16 l1 = __float2bfloat16(x1 - __bfloat162float(h1));
    __nv_bfloat162 hp = __nv_bfloat162(h0, h1);
    __nv_bfloat162 lp = __nv_bfloat162(l0, l1);
    h = *reinterpret_cast<uint32_t*>(&hp);
    l = *reinterpret_cast<uint32_t*>(&lp);
}
#define CP16(dst, src) \
    asm volatile("cp.async.cg.shared.global [%0], [%1], 16;" :: "r"(dst), "l"(src))
#define CP_COMMIT_WAIT() do { \
    asm volatile("cp.async.commit_group;"); \
    asm volatile("cp.async.wait_group 0;"); \
} while (0)

// ---------------- prologue: fp32 -> bf16 hi/lo split ----------------
__global__ void __launch_bounds__(256)
split_kernel(const float* __restrict__ src,
             __nv_bfloat16* __restrict__ hi,
             __nv_bfloat16* __restrict__ lo)
{
    int i = blockIdx.x * 256 + threadIdx.x;       // float4 index
    float4 x = ((const float4*)src)[i];
    uint32_t h01, l01, h23, l23;
    split2(x.x, x.y, h01, l01);
    split2(x.z, x.w, h23, l23);
    ((uint2*)hi)[i] = make_uint2(h01, h23);
    ((uint2*)lo)[i] = make_uint2(l01, l23);
}

// ---------------- main fused attention ----------------
__global__ void __launch_bounds__(NT, 2)
attn_tc_kernel(const float* __restrict__ mask,
               float* __restrict__ out_o,
               float* __restrict__ out_attn)
{
    extern __shared__ char smc[];
    float* Ef = (float*)(smc + OFF_EF);
    float* mc = (float*)(smc + OFF_MC);
    float (*rsp)[4] = (float (*)[4])(smc + OFF_RS);
    float* rinv = (float*)(smc + OFF_RI);
    float* Ob = (float*)(smc + OFF_KH);   // reused after j-loop

    const int bh  = blockIdx.y;
    const int i0  = blockIdx.x * TI;
    const int b   = bh >> 3;             // H = 8
    const int tid = threadIdx.x;
    const int L   = tid & 31;
    const int w   = tid >> 5;            // warp 0..7
    const int wi  = w & 1;               // 16-row half
    const int wj  = w >> 1;              // 0..3 -> 16-col (=k) group
    const int g   = L >> 2;
    const int t   = L & 3;

    const uint32_t khB = smem_u32(smc + OFF_KH);
    const uint32_t vhB = smem_u32(smc + OFF_VH);
    const uint32_t qhB = smem_u32(smc + OFF_QH);

    // column mask term: 0 or 1e9
    for (int j = tid; j < LEN; j += NT) {
        float mv = mask[b * LEN + j];
        mc[j] = (mv == -10000.0f) ? 1e9f : mv;
    }

    // ---- Q staging: pre-split bf16 hi/lo, 32x64, cp.async ----
    {
        const __nv_bfloat16* qh_g = g_qh + ((size_t)bh * LEN + i0) * DIM;
        const __nv_bfloat16* ql_g = g_ql + ((size_t)bh * LEN + i0) * DIM;
        int row = tid >> 3;
        int ch  = (tid & 7) * 8;
        uint32_t doff = (uint32_t)(row * PB + ch) * 2;
        CP16(qhB + doff, qh_g + row * DIM + ch);
        CP16(qhB + (OFF_QL - OFF_QH) + doff, ql_g + row * DIM + ch);
        CP_COMMIT_WAIT();
    }
    __syncthreads();

    // persistent Q fragments
    uint32_t qa_h[4][4], qa_l[4][4];
    {
        int arow = wi * 16 + (L & 15);
        int acol = (L >> 4) * 8;
        #pragma unroll
        for (int ks = 0; ks < 4; ks++) {
            uint32_t a = qhB + (uint32_t)(arow * PB + ks * 16 + acol) * 2;
            ldsm4(qa_h[ks], a);
            ldsm4(qa_l[ks], a + (OFF_QL - OFF_QH));
        }
    }

    float oacc[8][4];
    #pragma unroll
    for (int n = 0; n < 8; n++)
        #pragma unroll
        for (int c = 0; c < 4; c++) oacc[n][c] = 0.0f;
    float rs0 = 0.0f, rs1 = 0.0f;

    const int r0l = wi * 16 + g;
    const int r1l = r0l + 8;

    // GEMM1 B (K) addressing
    const int b1row  = wj * 16 + ((L >> 4) & 1) * 8 + (L & 7);
    const int b1colh = ((L >> 3) & 1) * 8;
    // GEMM2 B (V, trans) addressing: rows = this warp's k-slice
    const int b2row  = wj * 16 + ((L >> 3) & 1) * 8 + (L & 7);
    const int b2colh = (L >> 4) * 8;

    const bool rowM0 = (mc[i0 + r0l] != 0.0f);
    const bool rowM1 = (mc[i0 + r1l] != 0.0f);

    const __nv_bfloat16* kh_b = g_kh + (size_t)bh * LEN * DIM;
    const __nv_bfloat16* kl_b = g_kl + (size_t)bh * LEN * DIM;
    const __nv_bfloat16* vh_b = g_vh + (size_t)bh * LEN * DIM;
    const __nv_bfloat16* vl_b = g_vl + (size_t)bh * LEN * DIM;

    for (int jt = 0; jt < NJT; jt++) {
        const int j0 = jt * 64;
        __syncthreads();   // prior tile's consumers done before overwrite

        // ---- stage K/V hi/lo tiles (64x64 bf16 each) via cp.async ----
        {
            const __nv_bfloat16* khg = kh_b + (size_t)j0 * DIM;
            const __nv_bfloat16* klg = kl_b + (size_t)j0 * DIM;
            const __nv_bfloat16* vhg = vh_b + (size_t)j0 * DIM;
            const __nv_bfloat16* vlg = vl_b + (size_t)j0 * DIM;
            #pragma unroll
            for (int it = 0; it < 2; it++) {
                int lin = it * NT + tid;      // 0..511 chunk index
                int row = lin >> 3;
                int ch  = (lin & 7) * 8;
                uint32_t doff = (uint32_t)(row * PB + ch) * 2;
                int soff = row * DIM + ch;
                CP16(khB + doff, khg + soff);
                CP16(khB + (OFF_KL - OFF_KH) + doff, klg + soff);
                CP16(vhB + doff, vhg + soff);
                CP16(vhB + (OFF_VL - OFF_VH) + doff, vlg + soff);
            }
            CP_COMMIT_WAIT();
        }
        __syncthreads();

        // ---- GEMM1: S(16x16 per warp) = Q.K^T, 3-pass bf16 split ----
        float sacc[2][4];
        #pragma unroll
        for (int n = 0; n < 2; n++)
            #pragma unroll
            for (int c = 0; c < 4; c++) sacc[n][c] = 0.0f;

        #pragma unroll
        for (int ks = 0; ks < 4; ks++) {
            uint32_t addr = khB + (uint32_t)(b1row * PB + ks * 16 + b1colh) * 2;
            uint32_t bh4[4], bl4[4];
            ldsm4(bh4, addr);
            ldsm4(bl4, addr + (OFF_KL - OFF_KH));
            mma_bf16(sacc[0], qa_h[ks], bh4[0], bh4[1]);
            mma_bf16(sacc[1], qa_h[ks], bh4[2], bh4[3]);
            mma_bf16(sacc[0], qa_h[ks], bl4[0], bl4[1]);
            mma_bf16(sacc[1], qa_h[ks], bl4[2], bl4[3]);
            mma_bf16(sacc[0], qa_l[ks], bh4[0], bh4[1]);
            mma_bf16(sacc[1], qa_l[ks], bh4[2], bh4[3]);
        }

        // ---- epilogue: exp+mask -> Ef (f32) + A-fragments in registers ----
        uint32_t ah[4], al[4];
        #pragma unroll
        for (int nb = 0; nb < 2; nb++) {
            int lcol = wj * 16 + nb * 8 + 2 * t;
            int jj = j0 + lcol;
            float mj0 = mc[jj], mj1 = mc[jj + 1];
            float u0 = (mj0 == 0.0f) ? 1.0f : 0.0f;
            float u1 = (mj1 == 0.0f) ? 1.0f : 0.0f;
            float e00 = rowM0 ? u0 : __expf(fmaf(sacc[nb][0], 0.125f, -mj0));
            float e01 = rowM0 ? u1 : __expf(fmaf(sacc[nb][1], 0.125f, -mj1));
            float e10 = rowM1 ? u0 : __expf(fmaf(sacc[nb][2], 0.125f, -mj0));
            float e11 = rowM1 ? u1 : __expf(fmaf(sacc[nb][3], 0.125f, -mj1));
            rs0 += e00 + e01;
            rs1 += e10 + e11;
            *(float2*)&Ef[r0l * PEF + jj] = make_float2(e00, e01);
            *(float2*)&Ef[r1l * PEF + jj] = make_float2(e10, e11);
            // C-frag == A-frag layout: pack directly for GEMM2
            split2(e00, e01, ah[2 * nb],     al[2 * nb]);
            split2(e10, e11, ah[2 * nb + 1], al[2 * nb + 1]);
        }

        // ---- GEMM2: partial O(16x64) += E_slice(16x16) . V_slice(16x64) ----
        #pragma unroll
        for (int dc = 0; dc < 4; dc++) {
            uint32_t vaddr = vhB + (uint32_t)(b2row * PB + dc * 16 + b2colh) * 2;
            uint32_t vh4[4], vl4[4];
            ldsm4t(vh4, vaddr);
            ldsm4t(vl4, vaddr + (OFF_VL - OFF_VH));
            mma_bf16(oacc[2 * dc],     ah, vh4[0], vh4[1]);
            mma_bf16(oacc[2 * dc + 1], ah, vh4[2], vh4[3]);
            mma_bf16(oacc[2 * dc],     ah, vl4[0], vl4[1]);
            mma_bf16(oacc[2 * dc + 1], ah, vl4[2], vl4[3]);
            mma_bf16(oacc[2 * dc],     al, vh4[0], vh4[1]);
            mma_bf16(oacc[2 * dc + 1], al, vh4[2], vh4[3]);
        }
    }

    // ---- rowsum reduction ----
    rs0 += __shfl_xor_sync(0xffffffffu, rs0, 1);
    rs0 += __shfl_xor_sync(0xffffffffu, rs0, 2);
    rs1 += __shfl_xor_sync(0xffffffffu, rs1, 1);
    rs1 += __shfl_xor_sync(0xffffffffu, rs1, 2);

    __syncthreads();   // all GEMM2 smem reads done; K/V region now dead

    if (t == 0) {
        rsp[r0l][wj] = rs0;
        rsp[r1l][wj] = rs1;
    }
    // dump partial O to Obuf[wj]
    #pragma unroll
    for (int nb = 0; nb < 8; nb++) {
        int col = nb * 8 + 2 * t;
        *(float2*)&Ob[wj * (32 * OBP) + r0l * OBP + col] = make_float2(oacc[nb][0], oacc[nb][1]);
        *(float2*)&Ob[wj * (32 * OBP) + r1l * OBP + col] = make_float2(oacc[nb][2], oacc[nb][3]);
    }
    __syncthreads();

    if (tid < TI)
        rinv[tid] = 1.0f / (rsp[tid][0] + rsp[tid][1] + rsp[tid][2] + rsp[tid][3]);
    __syncthreads();

    // ---- O reduce across 4 k-slices + write ----
    if (out_o) {
        int row = tid >> 3;
        int c8  = (tid & 7) * 8;
        float s[8];
        #pragma unroll
        for (int i = 0; i < 8; i++) s[i] = 0.0f;
        #pragma unroll
        for (int p = 0; p < 4; p++) {
            const float* src = &Ob[p * (32 * OBP) + row * OBP + c8];
            #pragma unroll
            for (int i = 0; i < 8; i++) s[i] += src[i];
        }
        float inv = rinv[row];
        float* ob = out_o + ((size_t)bh * LEN + i0 + row) * DIM + c8;
        float4 o0 = make_float4(s[0] * inv, s[1] * inv, s[2] * inv, s[3] * inv);
        float4 o1 = make_float4(s[4] * inv, s[5] * inv, s[6] * inv, s[7] * inv);
        *(float4*)ob = o0;
        *(float4*)(ob + 4) = o1;
    }

    // ---- attn write = Ef * rinv ----
    if (out_attn) {
        float* ab = out_attn + ((size_t)bh * LEN + i0) * LEN;
        #pragma unroll 4
        for (int i4 = tid; i4 < TI * (LEN / 4); i4 += NT) {
            int row = i4 >> 7;
            int col = (i4 & 127) * 4;
            float inv = rinv[row];
            float4 e = *(const float4*)&Ef[row * PEF + col];
            e.x *= inv; e.y *= inv; e.z *= inv; e.w *= inv;
            *(float4*)&ab[(size_t)row * LEN + col] = e;
        }
    }
}

extern "C" void kernel_launch(void* const* d_in, const int* in_sizes, int n_in,
                              void* d_out, int out_size)
{
    const float* q    = (const float*)d_in[0];
    const float* k    = (const float*)d_in[1];
    const float* v    = (const float*)d_in[2];
    const float* mask = (const float*)d_in[3];

    const long long O_ELEMS = (long long)BH * LEN * DIM;   // 4194304
    const long long A_ELEMS = (long long)BH * LEN * LEN;   // 33554432

    float* out = (float*)d_out;
    float* o_ptr = nullptr;
    float* a_ptr = nullptr;
    if ((long long)out_size >= O_ELEMS + A_ELEMS) {
        o_ptr = out;
        a_ptr = out + O_ELEMS;
    } else if ((long long)out_size == A_ELEMS) {
        a_ptr = out;
    } else {
        o_ptr = out;
    }

    __nv_bfloat16 *qh, *ql, *kh, *kl, *vh, *vl;
    cudaGetSymbolAddress((void**)&qh, g_qh);
    cudaGetSymbolAddress((void**)&ql, g_ql);
    cudaGetSymbolAddress((void**)&kh, g_kh);
    cudaGetSymbolAddress((void**)&kl, g_kl);
    cudaGetSymbolAddress((void**)&vh, g_vh);
    cudaGetSymbolAddress((void**)&vl, g_vl);

    const int nblk = NELEM / 4 / 256;   // 4096
    split_kernel<<<nblk, 256>>>(q, qh, ql);
    split_kernel<<<nblk, 256>>>(k, kh, kl);
    split_kernel<<<nblk, 256>>>(v, vh, vl);

    cudaFuncSetAttribute(attn_tc_kernel,
                         cudaFuncAttributeMaxDynamicSharedMemorySize, SMEM_BYTES);

    dim3 grid(LEN / TI, BH);   // (16, 128) = 2048 CTAs
    attn_tc_kernel<<<grid, NT, SMEM_BYTES>>>(mask, o_ptr, a_ptr);
}

// round 6
// speedup vs baseline: 1.0619x; 1.0619x over previous
#include <cuda_runtime.h>
#include <cuda_bf16.h>
#include <cstdint>
#include <cstddef>

// Problem constants: B=16, H=8, L=512, D=64
#define BH   128
#define LEN  512
#define DIM  64
#define TI   32          // q-rows per CTA
#define NT   256         // threads (8 warps, 2x4 warp grid)
#define NJT  8           // 512/64 j-tiles
#define PB   72          // bf16 smem pitch (144B rows, 16B-aligned)
#define NELEM (BH*LEN*DIM)

// smem layout (bytes)
// stage s (s=0,1) at s*STAGE_BYTES: KH +0, KL +9216, VH +18432, VL +27648
#define STAGE_BYTES 36864
#define OFF_Q   73728            // QH 4608, QL at +4608
#define OFF_MC  82944            // 512 f32
#define OFF_RS  84992            // 32 x 4 f32
#define OFF_RI  85504            // 32 f32
#define SMEM_BYTES 85760
// O-reduction buffer reuses stage-0 region after the loop: 4*32*66*4 = 33792 B
#define OBP 66

// pre-split bf16 hi/lo scratch (written by prologue kernel)
__device__ __nv_bfloat16 g_qh[NELEM];
__device__ __nv_bfloat16 g_ql[NELEM];
__device__ __nv_bfloat16 g_kh[NELEM];
__device__ __nv_bfloat16 g_kl[NELEM];
__device__ __nv_bfloat16 g_vh[NELEM];
__device__ __nv_bfloat16 g_vl[NELEM];

__device__ __forceinline__ uint32_t smem_u32(const void* p) {
    return (uint32_t)__cvta_generic_to_shared(p);
}
__device__ __forceinline__ void ldsm4(uint32_t* r, uint32_t a) {
    asm volatile("ldmatrix.sync.aligned.m8n8.x4.shared.b16 {%0,%1,%2,%3}, [%4];"
                 : "=r"(r[0]), "=r"(r[1]), "=r"(r[2]), "=r"(r[3]) : "r"(a));
}
__device__ __forceinline__ void ldsm4t(uint32_t* r, uint32_t a) {
    asm volatile("ldmatrix.sync.aligned.m8n8.x4.trans.shared.b16 {%0,%1,%2,%3}, [%4];"
                 : "=r"(r[0]), "=r"(r[1]), "=r"(r[2]), "=r"(r[3]) : "r"(a));
}
__device__ __forceinline__ void mma_bf16(float* c, const uint32_t* a, uint32_t b0, uint32_t b1) {
    asm volatile("mma.sync.aligned.m16n8k16.row.col.f32.bf16.bf16.f32 "
                 "{%0,%1,%2,%3}, {%4,%5,%6,%7}, {%8,%9}, {%0,%1,%2,%3};"
                 : "+f"(c[0]), "+f"(c[1]), "+f"(c[2]), "+f"(c[3])
                 : "r"(a[0]), "r"(a[1]), "r"(a[2]), "r"(a[3]), "r"(b0), "r"(b1));
}
__device__ __forceinline__ void split2(float x0, float x1, uint32_t& h, uint32_t& l) {
    __nv_bfloat16 h0 = __float2bfloat16(x0);
    __nv_bfloat16 h1 = __float2bfloat16(x1);
    __nv_bfloat16 l0 = __float2bfloat16(x0 - __bfloat162float(h0));
    __nv_bfloat16 l1 = __float2bfloat16(x1 - __bfloat162float(h1));
    __nv_bfloat162 hp = __nv_bfloat162(h0, h1);
    __nv_bfloat162 lp = __nv_bfloat162(l0, l1);
    h = *reinterpret_cast<uint32_t*>(&hp);
    l = *reinterpret_cast<uint32_t*>(&lp);
}
#define CP16(dst, src) \
    asm volatile("cp.async.cg.shared.global [%0], [%1], 16;" :: "r"(dst), "l"(src))
#define CP_COMMIT() asm volatile("cp.async.commit_group;")
#define CP_WAIT0()  asm volatile("cp.async.wait_group 0;")

// ---------------- prologue: fp32 -> bf16 hi/lo split (all 3 tensors) ----------------
__global__ void __launch_bounds__(256)
split3_kernel(const float* __restrict__ q,
              const float* __restrict__ k,
              const float* __restrict__ v)
{
    int which = blockIdx.y;
    const float* src = (which == 0) ? q : (which == 1) ? k : v;
    __nv_bfloat16* hi = (which == 0) ? g_qh : (which == 1) ? g_kh : g_vh;
    __nv_bfloat16* lo = (which == 0) ? g_ql : (which == 1) ? g_kl : g_vl;

    int i = blockIdx.x * 256 + threadIdx.x;       // float4 index
    float4 x = ((const float4*)src)[i];
    uint32_t h01, l01, h23, l23;
    split2(x.x, x.y, h01, l01);
    split2(x.z, x.w, h23, l23);
    ((uint2*)hi)[i] = make_uint2(h01, h23);
    ((uint2*)lo)[i] = make_uint2(l01, l23);
}

// ---------------- main fused attention ----------------
__global__ void __launch_bounds__(NT, 2)
attn_tc_kernel(const float* __restrict__ mask,
               float* __restrict__ out_o,
               float* __restrict__ out_attn)
{
    extern __shared__ char smc[];
    float* mc = (float*)(smc + OFF_MC);
    float (*rsp)[4] = (float (*)[4])(smc + OFF_RS);
    float* rinv = (float*)(smc + OFF_RI);
    float* Ob = (float*)smc;              // reuses stage 0 after the loop

    const int bh  = blockIdx.y;
    const int i0  = blockIdx.x * TI;
    const int b   = bh >> 3;              // H = 8
    const int tid = threadIdx.x;
    const int L   = tid & 31;
    const int w   = tid >> 5;             // warp 0..7
    const int wi  = w & 1;                // 16-row half
    const int wj  = w >> 1;               // 0..3 -> 16-col (=k) group
    const int g   = L >> 2;
    const int t   = L & 3;

    const uint32_t smB = smem_u32(smc);
    const uint32_t qhB = smB + OFF_Q;

    // column mask term: 0 or 1e9
    for (int j = tid; j < LEN; j += NT) {
        float mv = mask[b * LEN + j];
        mc[j] = (mv == -10000.0f) ? 1e9f : mv;
    }

    const __nv_bfloat16* kh_b = g_kh + (size_t)bh * LEN * DIM;
    const __nv_bfloat16* kl_b = g_kl + (size_t)bh * LEN * DIM;
    const __nv_bfloat16* vh_b = g_vh + (size_t)bh * LEN * DIM;
    const __nv_bfloat16* vl_b = g_vl + (size_t)bh * LEN * DIM;

    // per-thread cp.async addressing for K/V tiles
    const int cprow0 = tid >> 3;              // rows tid/8 and tid/8+32
    const int cpch   = (tid & 7) * 8;
    const uint32_t cpdoff0 = (uint32_t)(cprow0 * PB + cpch) * 2;
    const uint32_t cpdoff1 = (uint32_t)((cprow0 + 32) * PB + cpch) * 2;

    // issue Q staging (pre-split bf16 hi/lo)
    {
        const __nv_bfloat16* qh_g = g_qh + ((size_t)bh * LEN + i0) * DIM;
        const __nv_bfloat16* ql_g = g_ql + ((size_t)bh * LEN + i0) * DIM;
        uint32_t doff = cpdoff0;              // rows 0..31
        int soff = cprow0 * DIM + cpch;
        CP16(qhB + doff, qh_g + soff);
        CP16(qhB + 4608 + doff, ql_g + soff);
        CP_COMMIT();
    }
    // issue tile 0 into stage 0
    {
        int soff0 = cprow0 * DIM + cpch;
        int soff1 = (cprow0 + 32) * DIM + cpch;
        uint32_t s0 = smB;
        CP16(s0 + cpdoff0,          kh_b + soff0);
        CP16(s0 + cpdoff1,          kh_b + soff1);
        CP16(s0 + 9216  + cpdoff0,  kl_b + soff0);
        CP16(s0 + 9216  + cpdoff1,  kl_b + soff1);
        CP16(s0 + 18432 + cpdoff0,  vh_b + soff0);
        CP16(s0 + 18432 + cpdoff1,  vh_b + soff1);
        CP16(s0 + 27648 + cpdoff0,  vl_b + soff0);
        CP16(s0 + 27648 + cpdoff1,  vl_b + soff1);
        CP_COMMIT();
    }
    CP_WAIT0();
    __syncthreads();

    // persistent Q fragments
    uint32_t qa_h[4][4], qa_l[4][4];
    {
        int arow = wi * 16 + (L & 15);
        int acol = (L >> 4) * 8;
        #pragma unroll
        for (int ks = 0; ks < 4; ks++) {
            uint32_t a = qhB + (uint32_t)(arow * PB + ks * 16 + acol) * 2;
            ldsm4(qa_h[ks], a);
            ldsm4(qa_l[ks], a + 4608);
        }
    }

    float oacc[8][4];
    #pragma unroll
    for (int n = 0; n < 8; n++)
        #pragma unroll
        for (int c = 0; c < 4; c++) oacc[n][c] = 0.0f;
    float rs0 = 0.0f, rs1 = 0.0f;

    const int r0l = wi * 16 + g;
    const int r1l = r0l + 8;

    const int b1row  = wj * 16 + ((L >> 4) & 1) * 8 + (L & 7);
    const int b1colh = ((L >> 3) & 1) * 8;
    const int b2row  = wj * 16 + ((L >> 3) & 1) * 8 + (L & 7);
    const int b2colh = (L >> 4) * 8;

    const bool rowM0 = (mc[i0 + r0l] != 0.0f);
    const bool rowM1 = (mc[i0 + r1l] != 0.0f);

    float* ab = out_attn ? out_attn + ((size_t)bh * LEN + i0) * LEN : nullptr;

    for (int jt = 0; jt < NJT; jt++) {
        const uint32_t stB = smB + (uint32_t)(jt & 1) * STAGE_BYTES;

        // prefetch next tile into the other stage (its readers finished
        // before the __syncthreads at the end of the previous iteration)
        if (jt + 1 < NJT) {
            const int j1 = (jt + 1) * 64;
            uint32_t s1 = smB + (uint32_t)((jt + 1) & 1) * STAGE_BYTES;
            int soff0 = (j1 + cprow0) * DIM + cpch;
            int soff1 = (j1 + cprow0 + 32) * DIM + cpch;
            CP16(s1 + cpdoff0,          kh_b + soff0);
            CP16(s1 + cpdoff1,          kh_b + soff1);
            CP16(s1 + 9216  + cpdoff0,  kl_b + soff0);
            CP16(s1 + 9216  + cpdoff1,  kl_b + soff1);
            CP16(s1 + 18432 + cpdoff0,  vh_b + soff0);
            CP16(s1 + 18432 + cpdoff1,  vh_b + soff1);
            CP16(s1 + 27648 + cpdoff0,  vl_b + soff0);
            CP16(s1 + 27648 + cpdoff1,  vl_b + soff1);
            CP_COMMIT();
        }

        // ---- GEMM1: S(16x16 per warp) = Q.K^T, 3-pass bf16 split ----
        float sacc[2][4];
        #pragma unroll
        for (int n = 0; n < 2; n++)
            #pragma unroll
            for (int c = 0; c < 4; c++) sacc[n][c] = 0.0f;

        #pragma unroll
        for (int ks = 0; ks < 4; ks++) {
            uint32_t addr = stB + (uint32_t)(b1row * PB + ks * 16 + b1colh) * 2;
            uint32_t bh4[4], bl4[4];
            ldsm4(bh4, addr);
            ldsm4(bl4, addr + 9216);
            mma_bf16(sacc[0], qa_h[ks], bh4[0], bh4[1]);
            mma_bf16(sacc[1], qa_h[ks], bh4[2], bh4[3]);
            mma_bf16(sacc[0], qa_h[ks], bl4[0], bl4[1]);
            mma_bf16(sacc[1], qa_h[ks], bl4[2], bl4[3]);
            mma_bf16(sacc[0], qa_l[ks], bh4[0], bh4[1]);
            mma_bf16(sacc[1], qa_l[ks], bh4[2], bh4[3]);
        }

        // ---- epilogue: exp+mask -> attn gmem (unnormalized) + A-frags ----
        const int j0 = jt * 64;
        uint32_t ah[4], al[4];
        #pragma unroll
        for (int nb = 0; nb < 2; nb++) {
            int lcol = wj * 16 + nb * 8 + 2 * t;
            int jj = j0 + lcol;
            float mj0 = mc[jj], mj1 = mc[jj + 1];
            float u0 = (mj0 == 0.0f) ? 1.0f : 0.0f;
            float u1 = (mj1 == 0.0f) ? 1.0f : 0.0f;
            float e00 = rowM0 ? u0 : __expf(fmaf(sacc[nb][0], 0.125f, -mj0));
            float e01 = rowM0 ? u1 : __expf(fmaf(sacc[nb][1], 0.125f, -mj1));
            float e10 = rowM1 ? u0 : __expf(fmaf(sacc[nb][2], 0.125f, -mj0));
            float e11 = rowM1 ? u1 : __expf(fmaf(sacc[nb][3], 0.125f, -mj1));
            rs0 += e00 + e01;
            rs1 += e10 + e11;
            if (ab) {
                *(float2*)&ab[(size_t)r0l * LEN + jj] = make_float2(e00, e01);
                *(float2*)&ab[(size_t)r1l * LEN + jj] = make_float2(e10, e11);
            }
            split2(e00, e01, ah[2 * nb],     al[2 * nb]);
            split2(e10, e11, ah[2 * nb + 1], al[2 * nb + 1]);
        }

        // ---- GEMM2: partial O(16x64) += E_slice(16x16) . V_slice(16x64) ----
        #pragma unroll
        for (int dc = 0; dc < 4; dc++) {
            uint32_t vaddr = stB + 18432 + (uint32_t)(b2row * PB + dc * 16 + b2colh) * 2;
            uint32_t vh4[4], vl4[4];
            ldsm4t(vh4, vaddr);
            ldsm4t(vl4, vaddr + 9216);
            mma_bf16(oacc[2 * dc],     ah, vh4[0], vh4[1]);
            mma_bf16(oacc[2 * dc + 1], ah, vh4[2], vh4[3]);
            mma_bf16(oacc[2 * dc],     ah, vl4[0], vl4[1]);
            mma_bf16(oacc[2 * dc + 1], ah, vl4[2], vl4[3]);
            mma_bf16(oacc[2 * dc],     al, vh4[0], vh4[1]);
            mma_bf16(oacc[2 * dc + 1], al, vh4[2], vh4[3]);
        }

        CP_WAIT0();       // next tile's loads done (overlapped with compute)
        __syncthreads();  // all warps done with this stage; staged data visible
    }

    // ---- rowsum reduction ----
    rs0 += __shfl_xor_sync(0xffffffffu, rs0, 1);
    rs0 += __shfl_xor_sync(0xffffffffu, rs0, 2);
    rs1 += __shfl_xor_sync(0xffffffffu, rs1, 1);
    rs1 += __shfl_xor_sync(0xffffffffu, rs1, 2);
    if (t == 0) {
        rsp[r0l][wj] = rs0;
        rsp[r1l][wj] = rs1;
    }
    // dump partial O into the (now dead) stage-0 region
    #pragma unroll
    for (int nb = 0; nb < 8; nb++) {
        int col = nb * 8 + 2 * t;
        *(float2*)&Ob[wj * (32 * OBP) + r0l * OBP + col] = make_float2(oacc[nb][0], oacc[nb][1]);
        *(float2*)&Ob[wj * (32 * OBP) + r1l * OBP + col] = make_float2(oacc[nb][2], oacc[nb][3]);
    }
    __syncthreads();

    if (tid < TI)
        rinv[tid] = 1.0f / (rsp[tid][0] + rsp[tid][1] + rsp[tid][2] + rsp[tid][3]);
    __syncthreads();

    // ---- O reduce across 4 k-slices + write ----
    if (out_o) {
        int row = tid >> 3;
        int c8  = (tid & 7) * 8;
        float s[8];
        #pragma unroll
        for (int i = 0; i < 8; i++) s[i] = 0.0f;
        #pragma unroll
        for (int p = 0; p < 4; p++) {
            const float* src = &Ob[p * (32 * OBP) + row * OBP + c8];
            #pragma unroll
            for (int i = 0; i < 8; i++) s[i] += src[i];
        }
        float inv = rinv[row];
        float* ob = out_o + ((size_t)bh * LEN + i0 + row) * DIM + c8;
        *(float4*)ob       = make_float4(s[0] * inv, s[1] * inv, s[2] * inv, s[3] * inv);
        *(float4*)(ob + 4) = make_float4(s[4] * inv, s[5] * inv, s[6] * inv, s[7] * inv);
    }

    // ---- normalize attn in place (block just wrote it; L2-hot) ----
    if (ab) {
        #pragma unroll 4
        for (int i4 = tid; i4 < TI * (LEN / 4); i4 += NT) {
            int row = i4 >> 7;
            int col = (i4 & 127) * 4;
            float inv = rinv[row];
            float4 e = *(const float4*)&ab[(size_t)row * LEN + col];
            e.x *= inv; e.y *= inv; e.z *= inv; e.w *= inv;
            *(float4*)&ab[(size_t)row * LEN + col] = e;
        }
    }
}

extern "C" void kernel_launch(void* const* d_in, const int* in_sizes, int n_in,
                              void* d_out, int out_size)
{
    const float* q    = (const float*)d_in[0];
    const float* k    = (const float*)d_in[1];
    const float* v    = (const float*)d_in[2];
    const float* mask = (const float*)d_in[3];

    const long long O_ELEMS = (long long)BH * LEN * DIM;   // 4194304
    const long long A_ELEMS = (long long)BH * LEN * LEN;   // 33554432

    float* out = (float*)d_out;
    float* o_ptr = nullptr;
    float* a_ptr = nullptr;
    if ((long long)out_size >= O_ELEMS + A_ELEMS) {
        o_ptr = out;
        a_ptr = out + O_ELEMS;
    } else if ((long long)out_size == A_ELEMS) {
        a_ptr = out;
    } else {
        o_ptr = out;
    }

    dim3 sgrid(NELEM / 4 / 256, 3);
    split3_kernel<<<sgrid, 256>>>(q, k, v);

    cudaFuncSetAttribute(attn_tc_kernel,
                         cudaFuncAttributeMaxDynamicSharedMemorySize, SMEM_BYTES);

    dim3 grid(LEN / TI, BH);   // (16, 128) = 2048 CTAs
    attn_tc_kernel<<<grid, NT, SMEM_BYTES>>>(mask, o_ptr, a_ptr);
}

// round 7
// speedup vs baseline: 1.0638x; 1.0018x over previous
#include <cuda_runtime.h>
#include <cuda_bf16.h>
#include <cstdint>
#include <cstddef>

// Problem constants: B=16, H=8, L=512, D=64
#define BH   128
#define LEN  512
#define DIM  64
#define TI   32          // q-rows per CTA
#define NT   256         // threads (8 warps, 2x4 warp grid)
#define NJT  8           // 512/64 j-tiles
#define PB   72          // bf16 smem pitch (144B rows, 16B-aligned)
#define NELEM (BH*LEN*DIM)

// smem layout (bytes)
// stage s (s=0,1) at s*STAGE_BYTES: KH +0, KL +9216, VH +18432, VL +27648
#define STAGE_BYTES 36864
#define OFF_Q   73728            // QH 4608, QL at +4608
#define OFF_MC  82944            // 512 f32
#define OFF_RS  84992            // 32 x 4 f32
#define OFF_RI  85504            // 32 f32
#define SMEM_BYTES 85760
// O-reduction buffer reuses stage-0 region after the loop: 4*32*66*4 = 33792 B
#define OBP 66

// pre-split bf16 hi/lo scratch for K and V (written by prologue kernel)
__device__ __nv_bfloat16 g_kh[NELEM];
__device__ __nv_bfloat16 g_kl[NELEM];
__device__ __nv_bfloat16 g_vh[NELEM];
__device__ __nv_bfloat16 g_vl[NELEM];

__device__ __forceinline__ uint32_t smem_u32(const void* p) {
    return (uint32_t)__cvta_generic_to_shared(p);
}
__device__ __forceinline__ void ldsm4(uint32_t* r, uint32_t a) {
    asm volatile("ldmatrix.sync.aligned.m8n8.x4.shared.b16 {%0,%1,%2,%3}, [%4];"
                 : "=r"(r[0]), "=r"(r[1]), "=r"(r[2]), "=r"(r[3]) : "r"(a));
}
__device__ __forceinline__ void ldsm4t(uint32_t* r, uint32_t a) {
    asm volatile("ldmatrix.sync.aligned.m8n8.x4.trans.shared.b16 {%0,%1,%2,%3}, [%4];"
                 : "=r"(r[0]), "=r"(r[1]), "=r"(r[2]), "=r"(r[3]) : "r"(a));
}
__device__ __forceinline__ void mma_bf16(float* c, const uint32_t* a, uint32_t b0, uint32_t b1) {
    asm volatile("mma.sync.aligned.m16n8k16.row.col.f32.bf16.bf16.f32 "
                 "{%0,%1,%2,%3}, {%4,%5,%6,%7}, {%8,%9}, {%0,%1,%2,%3};"
                 : "+f"(c[0]), "+f"(c[1]), "+f"(c[2]), "+f"(c[3])
                 : "r"(a[0]), "r"(a[1]), "r"(a[2]), "r"(a[3]), "r"(b0), "r"(b1));
}
__device__ __forceinline__ void split2(float x0, float x1, uint32_t& h, uint32_t& l) {
    __nv_bfloat16 h0 = __float2bfloat16(x0);
    __nv_bfloat16 h1 = __float2bfloat16(x1);
    __nv_bfloat16 l0 = __float2bfloat16(x0 - __bfloat162float(h0));
    __nv_bfloat16 l1 = __float2bfloat16(x1 - __bfloat162float(h1));
    __nv_bfloat162 hp = __nv_bfloat162(h0, h1);
    __nv_bfloat162 lp = __nv_bfloat162(l0, l1);
    h = *reinterpret_cast<uint32_t*>(&hp);
    l = *reinterpret_cast<uint32_t*>(&lp);
}
#define CP16(dst, src) \
    asm volatile("cp.async.cg.shared.global [%0], [%1], 16;" :: "r"(dst), "l"(src))
#define CP_COMMIT() asm volatile("cp.async.commit_group;")
#define CP_WAIT0()  asm volatile("cp.async.wait_group 0;")

// ---------------- prologue: fp32 -> bf16 hi/lo split (K and V) ----------------
__global__ void __launch_bounds__(256)
split2_kernel(const float* __restrict__ k,
              const float* __restrict__ v)
{
    const float* src = (blockIdx.y == 0) ? k : v;
    __nv_bfloat16* hi = (blockIdx.y == 0) ? g_kh : g_vh;
    __nv_bfloat16* lo = (blockIdx.y == 0) ? g_kl : g_vl;

    int i = blockIdx.x * 256 + threadIdx.x;       // 8-float chunk index
    float4 x0 = ((const float4*)src)[2 * i];
    float4 x1 = ((const float4*)src)[2 * i + 1];
    uint4 h, l;
    split2(x0.x, x0.y, h.x, l.x);
    split2(x0.z, x0.w, h.y, l.y);
    split2(x1.x, x1.y, h.z, l.z);
    split2(x1.z, x1.w, h.w, l.w);
    ((uint4*)hi)[i] = h;
    ((uint4*)lo)[i] = l;
}

// ---------------- main fused attention ----------------
__global__ void __launch_bounds__(NT, 2)
attn_tc_kernel(const float* __restrict__ q,
               const float* __restrict__ mask,
               float* __restrict__ out_o,
               float* __restrict__ out_attn)
{
    extern __shared__ char smc[];
    float* mc = (float*)(smc + OFF_MC);
    float (*rsp)[4] = (float (*)[4])(smc + OFF_RS);
    float* rinv = (float*)(smc + OFF_RI);
    float* Ob = (float*)smc;              // reuses stage 0 after the loop
    __nv_bfloat16* Qh = (__nv_bfloat16*)(smc + OFF_Q);
    __nv_bfloat16* Ql = (__nv_bfloat16*)(smc + OFF_Q + 4608);

    const int bh  = blockIdx.y;
    const int i0  = blockIdx.x * TI;
    const int b   = bh >> 3;              // H = 8
    const int tid = threadIdx.x;
    const int L   = tid & 31;
    const int w   = tid >> 5;             // warp 0..7
    const int wi  = w & 1;                // 16-row half
    const int wj  = w >> 1;               // 0..3 -> 16-col (=k) group
    const int g   = L >> 2;
    const int t   = L & 3;

    const uint32_t smB = smem_u32(smc);
    const uint32_t qhB = smB + OFF_Q;

    const __nv_bfloat16* kh_b = g_kh + (size_t)bh * LEN * DIM;
    const __nv_bfloat16* kl_b = g_kl + (size_t)bh * LEN * DIM;
    const __nv_bfloat16* vh_b = g_vh + (size_t)bh * LEN * DIM;
    const __nv_bfloat16* vl_b = g_vl + (size_t)bh * LEN * DIM;

    // per-thread cp.async addressing for K/V tiles
    const int cprow0 = tid >> 3;              // rows tid/8 and tid/8+32
    const int cpch   = (tid & 7) * 8;
    const uint32_t cpdoff0 = (uint32_t)(cprow0 * PB + cpch) * 2;
    const uint32_t cpdoff1 = (uint32_t)((cprow0 + 32) * PB + cpch) * 2;

    // issue tile 0 into stage 0 first (loads fly under Q split below)
    {
        int soff0 = cprow0 * DIM + cpch;
        int soff1 = (cprow0 + 32) * DIM + cpch;
        uint32_t s0 = smB;
        CP16(s0 + cpdoff0,          kh_b + soff0);
        CP16(s0 + cpdoff1,          kh_b + soff1);
        CP16(s0 + 9216  + cpdoff0,  kl_b + soff0);
        CP16(s0 + 9216  + cpdoff1,  kl_b + soff1);
        CP16(s0 + 18432 + cpdoff0,  vh_b + soff0);
        CP16(s0 + 18432 + cpdoff1,  vh_b + soff1);
        CP16(s0 + 27648 + cpdoff0,  vl_b + soff0);
        CP16(s0 + 27648 + cpdoff1,  vl_b + soff1);
        CP_COMMIT();
    }

    // column mask term: 0 or 1e9
    for (int j = tid; j < LEN; j += NT) {
        float mv = mask[b * LEN + j];
        mc[j] = (mv == -10000.0f) ? 1e9f : mv;
    }

    // inline Q split: 32x64 fp32 -> bf16 hi/lo in smem
    {
        const float* qb = q + ((size_t)bh * LEN + i0) * DIM;
        #pragma unroll
        for (int it = 0; it < 2; it++) {
            int lin = it * NT + tid;             // 0..511 float4 chunks
            int row = lin >> 4;
            int c4  = (lin & 15) * 4;
            float4 x = *(const float4*)(qb + row * DIM + c4);
            uint32_t h01, l01, h23, l23;
            split2(x.x, x.y, h01, l01);
            split2(x.z, x.w, h23, l23);
            *(uint32_t*)&Qh[row * PB + c4]     = h01;
            *(uint32_t*)&Qh[row * PB + c4 + 2] = h23;
            *(uint32_t*)&Ql[row * PB + c4]     = l01;
            *(uint32_t*)&Ql[row * PB + c4 + 2] = l23;
        }
    }
    CP_WAIT0();
    __syncthreads();

    // persistent Q fragments
    uint32_t qa_h[4][4], qa_l[4][4];
    {
        int arow = wi * 16 + (L & 15);
        int acol = (L >> 4) * 8;
        #pragma unroll
        for (int ks = 0; ks < 4; ks++) {
            uint32_t a = qhB + (uint32_t)(arow * PB + ks * 16 + acol) * 2;
            ldsm4(qa_h[ks], a);
            ldsm4(qa_l[ks], a + 4608);
        }
    }

    float oacc[8][4];
    #pragma unroll
    for (int n = 0; n < 8; n++)
        #pragma unroll
        for (int c = 0; c < 4; c++) oacc[n][c] = 0.0f;
    float rs0 = 0.0f, rs1 = 0.0f;

    const int r0l = wi * 16 + g;
    const int r1l = r0l + 8;

    const int b1row  = wj * 16 + ((L >> 4) & 1) * 8 + (L & 7);
    const int b1colh = ((L >> 3) & 1) * 8;
    const int b2row  = wj * 16 + ((L >> 3) & 1) * 8 + (L & 7);
    const int b2colh = (L >> 4) * 8;

    const bool rowM0 = (mc[i0 + r0l] != 0.0f);
    const bool rowM1 = (mc[i0 + r1l] != 0.0f);

    float* ab = out_attn ? out_attn + ((size_t)bh * LEN + i0) * LEN : nullptr;

    for (int jt = 0; jt < NJT; jt++) {
        const uint32_t stB = smB + (uint32_t)(jt & 1) * STAGE_BYTES;

        // prefetch next tile into the other stage
        if (jt + 1 < NJT) {
            const int j1 = (jt + 1) * 64;
            uint32_t s1 = smB + (uint32_t)((jt + 1) & 1) * STAGE_BYTES;
            int soff0 = (j1 + cprow0) * DIM + cpch;
            int soff1 = (j1 + cprow0 + 32) * DIM + cpch;
            CP16(s1 + cpdoff0,          kh_b + soff0);
            CP16(s1 + cpdoff1,          kh_b + soff1);
            CP16(s1 + 9216  + cpdoff0,  kl_b + soff0);
            CP16(s1 + 9216  + cpdoff1,  kl_b + soff1);
            CP16(s1 + 18432 + cpdoff0,  vh_b + soff0);
            CP16(s1 + 18432 + cpdoff1,  vh_b + soff1);
            CP16(s1 + 27648 + cpdoff0,  vl_b + soff0);
            CP16(s1 + 27648 + cpdoff1,  vl_b + soff1);
            CP_COMMIT();
        }

        // ---- GEMM1: S(16x16 per warp) = Q.K^T, 3-pass bf16 split ----
        // Two independent accumulator chains per n-block: hh and cross.
        float shh[2][4], sx[2][4];
        #pragma unroll
        for (int n = 0; n < 2; n++)
            #pragma unroll
            for (int c = 0; c < 4; c++) { shh[n][c] = 0.0f; sx[n][c] = 0.0f; }

        #pragma unroll
        for (int ks = 0; ks < 4; ks++) {
            uint32_t addr = stB + (uint32_t)(b1row * PB + ks * 16 + b1colh) * 2;
            uint32_t bh4[4], bl4[4];
            ldsm4(bh4, addr);
            ldsm4(bl4, addr + 9216);
            mma_bf16(shh[0], qa_h[ks], bh4[0], bh4[1]);
            mma_bf16(shh[1], qa_h[ks], bh4[2], bh4[3]);
            mma_bf16(sx[0],  qa_h[ks], bl4[0], bl4[1]);
            mma_bf16(sx[1],  qa_h[ks], bl4[2], bl4[3]);
            mma_bf16(sx[0],  qa_l[ks], bh4[0], bh4[1]);
            mma_bf16(sx[1],  qa_l[ks], bh4[2], bh4[3]);
        }

        // ---- epilogue: exp+mask -> attn gmem (unnormalized) + A-frags ----
        const int j0 = jt * 64;
        uint32_t ah[4], al[4];
        #pragma unroll
        for (int nb = 0; nb < 2; nb++) {
            int lcol = wj * 16 + nb * 8 + 2 * t;
            int jj = j0 + lcol;
            float mj0 = mc[jj], mj1 = mc[jj + 1];
            float u0 = (mj0 == 0.0f) ? 1.0f : 0.0f;
            float u1 = (mj1 == 0.0f) ? 1.0f : 0.0f;
            float s00 = shh[nb][0] + sx[nb][0];
            float s01 = shh[nb][1] + sx[nb][1];
            float s10 = shh[nb][2] + sx[nb][2];
            float s11 = shh[nb][3] + sx[nb][3];
            float e00 = rowM0 ? u0 : __expf(fmaf(s00, 0.125f, -mj0));
            float e01 = rowM0 ? u1 : __expf(fmaf(s01, 0.125f, -mj1));
            float e10 = rowM1 ? u0 : __expf(fmaf(s10, 0.125f, -mj0));
            float e11 = rowM1 ? u1 : __expf(fmaf(s11, 0.125f, -mj1));
            rs0 += e00 + e01;
            rs1 += e10 + e11;
            if (ab) {
                *(float2*)&ab[(size_t)r0l * LEN + jj] = make_float2(e00, e01);
                *(float2*)&ab[(size_t)r1l * LEN + jj] = make_float2(e10, e11);
            }
            split2(e00, e01, ah[2 * nb],     al[2 * nb]);
            split2(e10, e11, ah[2 * nb + 1], al[2 * nb + 1]);
        }

        // ---- GEMM2: partial O(16x64) += E_slice(16x16) . V_slice(16x64) ----
        #pragma unroll
        for (int dc = 0; dc < 4; dc++) {
            uint32_t vaddr = stB + 18432 + (uint32_t)(b2row * PB + dc * 16 + b2colh) * 2;
            uint32_t vh4[4], vl4[4];
            ldsm4t(vh4, vaddr);
            ldsm4t(vl4, vaddr + 9216);
            mma_bf16(oacc[2 * dc],     ah, vh4[0], vh4[1]);
            mma_bf16(oacc[2 * dc + 1], ah, vh4[2], vh4[3]);
            mma_bf16(oacc[2 * dc],     ah, vl4[0], vl4[1]);
            mma_bf16(oacc[2 * dc + 1], ah, vl4[2], vl4[3]);
            mma_bf16(oacc[2 * dc],     al, vh4[0], vh4[1]);
            mma_bf16(oacc[2 * dc + 1], al, vh4[2], vh4[3]);
        }

        CP_WAIT0();       // next tile's loads done (overlapped with compute)
        __syncthreads();  // all warps done with this stage
    }

    // ---- rowsum reduction ----
    rs0 += __shfl_xor_sync(0xffffffffu, rs0, 1);
    rs0 += __shfl_xor_sync(0xffffffffu, rs0, 2);
    rs1 += __shfl_xor_sync(0xffffffffu, rs1, 1);
    rs1 += __shfl_xor_sync(0xffffffffu, rs1, 2);
    if (t == 0) {
        rsp[r0l][wj] = rs0;
        rsp[r1l][wj] = rs1;
    }
    // dump partial O into the (now dead) stage-0 region
    #pragma unroll
    for (int nb = 0; nb < 8; nb++) {
        int col = nb * 8 + 2 * t;
        *(float2*)&Ob[wj * (32 * OBP) + r0l * OBP + col] = make_float2(oacc[nb][0], oacc[nb][1]);
        *(float2*)&Ob[wj * (32 * OBP) + r1l * OBP + col] = make_float2(oacc[nb][2], oacc[nb][3]);
    }
    __syncthreads();

    if (tid < TI)
        rinv[tid] = 1.0f / (rsp[tid][0] + rsp[tid][1] + rsp[tid][2] + rsp[tid][3]);
    __syncthreads();

    // ---- O reduce across 4 k-slices + write ----
    if (out_o) {
        int row = tid >> 3;
        int c8  = (tid & 7) * 8;
        float s[8];
        #pragma unroll
        for (int i = 0; i < 8; i++) s[i] = 0.0f;
        #pragma unroll
        for (int p = 0; p < 4; p++) {
            const float* src = &Ob[p * (32 * OBP) + row * OBP + c8];
            #pragma unroll
            for (int i = 0; i < 8; i++) s[i] += src[i];
        }
        float inv = rinv[row];
        float* ob = out_o + ((size_t)bh * LEN + i0 + row) * DIM + c8;
        *(float4*)ob       = make_float4(s[0] * inv, s[1] * inv, s[2] * inv, s[3] * inv);
        *(float4*)(ob + 4) = make_float4(s[4] * inv, s[5] * inv, s[6] * inv, s[7] * inv);
    }

    // ---- normalize attn in place (CTA just wrote it; L2-hot) ----
    if (ab) {
        #pragma unroll 4
        for (int i4 = tid; i4 < TI * (LEN / 4); i4 += NT) {
            int row = i4 >> 7;
            int col = (i4 & 127) * 4;
            float inv = rinv[row];
            float4 e = *(const float4*)&ab[(size_t)row * LEN + col];
            e.x *= inv; e.y *= inv; e.z *= inv; e.w *= inv;
            *(float4*)&ab[(size_t)row * LEN + col] = e;
        }
    }
}

extern "C" void kernel_launch(void* const* d_in, const int* in_sizes, int n_in,
                              void* d_out, int out_size)
{
    const float* q    = (const float*)d_in[0];
    const float* k    = (const float*)d_in[1];
    const float* v    = (const float*)d_in[2];
    const float* mask = (const float*)d_in[3];

    const long long O_ELEMS = (long long)BH * LEN * DIM;   // 4194304
    const long long A_ELEMS = (long long)BH * LEN * LEN;   // 33554432

    float* out = (float*)d_out;
    float* o_ptr = nullptr;
    float* a_ptr = nullptr;
    if ((long long)out_size >= O_ELEMS + A_ELEMS) {
        o_ptr = out;
        a_ptr = out + O_ELEMS;
    } else if ((long long)out_size == A_ELEMS) {
        a_ptr = out;
    } else {
        o_ptr = out;
    }

    dim3 sgrid(NELEM / 8 / 256, 2);
    split2_kernel<<<sgrid, 256>>>(k, v);

    cudaFuncSetAttribute(attn_tc_kernel,
                         cudaFuncAttributeMaxDynamicSharedMemorySize, SMEM_BYTES);

    dim3 grid(LEN / TI, BH);   // (16, 128) = 2048 CTAs
    attn_tc_kernel<<<grid, NT, SMEM_BYTES>>>(q, mask, o_ptr, a_ptr);
}

// round 9
// speedup vs baseline: 1.0789x; 1.0142x over previous
#include <cuda_runtime.h>
#include <cuda_bf16.h>
#include <cstdint>
#include <cstddef>

// Problem constants: B=16, H=8, L=512, D=64
#define BH   128
#define LEN  512
#define DIM  64
#define TI   32          // q-rows per CTA
#define NT   256         // threads (8 warps, 2x4 warp grid)
#define NJT  8           // 512/64 j-tiles
#define PB   72          // bf16 smem pitch (144B rows, 16B-aligned)
#define NELEM (BH*LEN*DIM)

// smem layout (bytes)
// stage s (s=0,1) at s*STAGE_BYTES: KH +0, KL +9216, VH +18432, VL +27648
#define STAGE_BYTES 36864
#define OFF_Q   73728            // QH 4608, QL at +4608
#define OFF_MC  82944            // 512 f32
#define OFF_RS  84992            // 32 x 4 f32
#define OFF_RI  85504            // 32 f32
#define SMEM_BYTES 85760
// O-reduction buffer reuses stage-0 region after the loop: 4*32*66*4 = 33792 B
#define OBP 66

// pre-split bf16 hi/lo scratch for K and V (written by prologue kernel)
__device__ __nv_bfloat16 g_kh[NELEM];
__device__ __nv_bfloat16 g_kl[NELEM];
__device__ __nv_bfloat16 g_vh[NELEM];
__device__ __nv_bfloat16 g_vl[NELEM];

__device__ __forceinline__ uint32_t smem_u32(const void* p) {
    return (uint32_t)__cvta_generic_to_shared(p);
}
__device__ __forceinline__ void ldsm4(uint32_t* r, uint32_t a) {
    asm volatile("ldmatrix.sync.aligned.m8n8.x4.shared.b16 {%0,%1,%2,%3}, [%4];"
                 : "=r"(r[0]), "=r"(r[1]), "=r"(r[2]), "=r"(r[3]) : "r"(a));
}
__device__ __forceinline__ void ldsm4t(uint32_t* r, uint32_t a) {
    asm volatile("ldmatrix.sync.aligned.m8n8.x4.trans.shared.b16 {%0,%1,%2,%3}, [%4];"
                 : "=r"(r[0]), "=r"(r[1]), "=r"(r[2]), "=r"(r[3]) : "r"(a));
}
__device__ __forceinline__ void mma_bf16(float* c, const uint32_t* a, uint32_t b0, uint32_t b1) {
    asm volatile("mma.sync.aligned.m16n8k16.row.col.f32.bf16.bf16.f32 "
                 "{%0,%1,%2,%3}, {%4,%5,%6,%7}, {%8,%9}, {%0,%1,%2,%3};"
                 : "+f"(c[0]), "+f"(c[1]), "+f"(c[2]), "+f"(c[3])
                 : "r"(a[0]), "r"(a[1]), "r"(a[2]), "r"(a[3]), "r"(b0), "r"(b1));
}
__device__ __forceinline__ void split2(float x0, float x1, uint32_t& h, uint32_t& l) {
    __nv_bfloat16 h0 = __float2bfloat16(x0);
    __nv_bfloat16 h1 = __float2bfloat16(x1);
    __nv_bfloat16 l0 = __float2bfloat16(x0 - __bfloat162float(h0));
    __nv_bfloat16 l1 = __float2bfloat16(x1 - __bfloat162float(h1));
    __nv_bfloat162 hp = __nv_bfloat162(h0, h1);
    __nv_bfloat162 lp = __nv_bfloat162(l0, l1);
    h = *reinterpret_cast<uint32_t*>(&hp);
    l = *reinterpret_cast<uint32_t*>(&lp);
}
#define CP16(dst, src) \
    asm volatile("cp.async.cg.shared.global [%0], [%1], 16;" :: "r"(dst), "l"(src))
#define CP_COMMIT() asm volatile("cp.async.commit_group;")
#define CP_WAIT0()  asm volatile("cp.async.wait_group 0;")

// ---------------- prologue: fp32 -> bf16 hi/lo split (K and V) ----------------
__global__ void __launch_bounds__(256)
split2_kernel(const float* __restrict__ k,
              const float* __restrict__ v)
{
    const float* src = (blockIdx.y == 0) ? k : v;
    __nv_bfloat16* hi = (blockIdx.y == 0) ? g_kh : g_vh;
    __nv_bfloat16* lo = (blockIdx.y == 0) ? g_kl : g_vl;

    int i = blockIdx.x * 256 + threadIdx.x;       // 8-float chunk index
    float4 x0 = ((const float4*)src)[2 * i];
    float4 x1 = ((const float4*)src)[2 * i + 1];
    uint4 h, l;
    split2(x0.x, x0.y, h.x, l.x);
    split2(x0.z, x0.w, h.y, l.y);
    split2(x1.x, x1.y, h.z, l.z);
    split2(x1.z, x1.w, h.w, l.w);
    ((uint4*)hi)[i] = h;
    ((uint4*)lo)[i] = l;
}

// ---------------- main fused attention ----------------
__global__ void __launch_bounds__(NT, 2)
attn_tc_kernel(const float* __restrict__ q,
               const float* __restrict__ mask,
               float* __restrict__ out_o,
               float* __restrict__ out_attn)
{
    extern __shared__ char smc[];
    float* mc = (float*)(smc + OFF_MC);
    float (*rsp)[4] = (float (*)[4])(smc + OFF_RS);
    float* rinv = (float*)(smc + OFF_RI);
    float* Ob = (float*)smc;              // reuses stage 0 after the loop
    __nv_bfloat16* Qh = (__nv_bfloat16*)(smc + OFF_Q);
    __nv_bfloat16* Ql = (__nv_bfloat16*)(smc + OFF_Q + 4608);

    const int bh  = blockIdx.y;
    const int i0  = blockIdx.x * TI;
    const int b   = bh >> 3;              // H = 8
    const int tid = threadIdx.x;
    const int L   = tid & 31;
    const int w   = tid >> 5;             // warp 0..7
    const int wi  = w & 1;                // 16-row half
    const int wj  = w >> 1;               // 0..3 -> 16-col (=k) group
    const int g   = L >> 2;
    const int t   = L & 3;

    const uint32_t smB = smem_u32(smc);
    const uint32_t qhB = smB + OFF_Q;

    const __nv_bfloat16* kh_b = g_kh + (size_t)bh * LEN * DIM;
    const __nv_bfloat16* kl_b = g_kl + (size_t)bh * LEN * DIM;
    const __nv_bfloat16* vh_b = g_vh + (size_t)bh * LEN * DIM;
    const __nv_bfloat16* vl_b = g_vl + (size_t)bh * LEN * DIM;

    // per-thread cp.async addressing for K/V tiles
    const int cprow0 = tid >> 3;              // rows tid/8 and tid/8+32
    const int cpch   = (tid & 7) * 8;
    const uint32_t cpdoff0 = (uint32_t)(cprow0 * PB + cpch) * 2;
    const uint32_t cpdoff1 = (uint32_t)((cprow0 + 32) * PB + cpch) * 2;

    // issue tile 0 into stage 0 first (loads fly under Q split below)
    {
        int soff0 = cprow0 * DIM + cpch;
        int soff1 = (cprow0 + 32) * DIM + cpch;
        uint32_t s0 = smB;
        CP16(s0 + cpdoff0,          kh_b + soff0);
        CP16(s0 + cpdoff1,          kh_b + soff1);
        CP16(s0 + 9216  + cpdoff0,  kl_b + soff0);
        CP16(s0 + 9216  + cpdoff1,  kl_b + soff1);
        CP16(s0 + 18432 + cpdoff0,  vh_b + soff0);
        CP16(s0 + 18432 + cpdoff1,  vh_b + soff1);
        CP16(s0 + 27648 + cpdoff0,  vl_b + soff0);
        CP16(s0 + 27648 + cpdoff1,  vl_b + soff1);
        CP_COMMIT();
    }

    // column mask term: 0 or 1e9
    for (int j = tid; j < LEN; j += NT) {
        float mv = mask[b * LEN + j];
        mc[j] = (mv == -10000.0f) ? 1e9f : mv;
    }

    // inline Q split: 32x64 fp32 -> bf16 hi/lo in smem
    {
        const float* qb = q + ((size_t)bh * LEN + i0) * DIM;
        #pragma unroll
        for (int it = 0; it < 2; it++) {
            int lin = it * NT + tid;             // 0..511 float4 chunks
            int row = lin >> 4;
            int c4  = (lin & 15) * 4;
            float4 x = *(const float4*)(qb + row * DIM + c4);
            uint32_t h01, l01, h23, l23;
            split2(x.x, x.y, h01, l01);
            split2(x.z, x.w, h23, l23);
            *(uint32_t*)&Qh[row * PB + c4]     = h01;
            *(uint32_t*)&Qh[row * PB + c4 + 2] = h23;
            *(uint32_t*)&Ql[row * PB + c4]     = l01;
            *(uint32_t*)&Ql[row * PB + c4 + 2] = l23;
        }
    }
    CP_WAIT0();
    __syncthreads();

    // persistent Q fragments
    uint32_t qa_h[4][4], qa_l[4][4];
    {
        int arow = wi * 16 + (L & 15);
        int acol = (L >> 4) * 8;
        #pragma unroll
        for (int ks = 0; ks < 4; ks++) {
            uint32_t a = qhB + (uint32_t)(arow * PB + ks * 16 + acol) * 2;
            ldsm4(qa_h[ks], a);
            ldsm4(qa_l[ks], a + 4608);
        }
    }

    float oacc[8][4];
    #pragma unroll
    for (int n = 0; n < 8; n++)
        #pragma unroll
        for (int c = 0; c < 4; c++) oacc[n][c] = 0.0f;
    float rs0 = 0.0f, rs1 = 0.0f;

    const int r0l = wi * 16 + g;
    const int r1l = r0l + 8;

    const int b1row  = wj * 16 + ((L >> 4) & 1) * 8 + (L & 7);
    const int b1colh = ((L >> 3) & 1) * 8;
    const int b2row  = wj * 16 + ((L >> 3) & 1) * 8 + (L & 7);
    const int b2colh = (L >> 4) * 8;

    const bool rowM0 = (mc[i0 + r0l] != 0.0f);
    const bool rowM1 = (mc[i0 + r1l] != 0.0f);

    float* ab = out_attn ? out_attn + ((size_t)bh * LEN + i0) * LEN : nullptr;

    for (int jt = 0; jt < NJT; jt++) {
        const uint32_t stB = smB + (uint32_t)(jt & 1) * STAGE_BYTES;

        // prefetch next tile into the other stage
        if (jt + 1 < NJT) {
            const int j1 = (jt + 1) * 64;
            uint32_t s1 = smB + (uint32_t)((jt + 1) & 1) * STAGE_BYTES;
            int soff0 = (j1 + cprow0) * DIM + cpch;
            int soff1 = (j1 + cprow0 + 32) * DIM + cpch;
            CP16(s1 + cpdoff0,          kh_b + soff0);
            CP16(s1 + cpdoff1,          kh_b + soff1);
            CP16(s1 + 9216  + cpdoff0,  kl_b + soff0);
            CP16(s1 + 9216  + cpdoff1,  kl_b + soff1);
            CP16(s1 + 18432 + cpdoff0,  vh_b + soff0);
            CP16(s1 + 18432 + cpdoff1,  vh_b + soff1);
            CP16(s1 + 27648 + cpdoff0,  vl_b + soff0);
            CP16(s1 + 27648 + cpdoff1,  vl_b + soff1);
            CP_COMMIT();
        }

        // ---- GEMM1: S(16x16 per warp) = Q.K^T, 3-pass bf16 split ----
        // Software-pipelined: ldsm for ks+1 issued before MMAs of ks.
        float sacc[2][4];
        #pragma unroll
        for (int n = 0; n < 2; n++)
            #pragma unroll
            for (int c = 0; c < 4; c++) sacc[n][c] = 0.0f;

        uint32_t kbh[2][4], kbl[2][4];
        {
            uint32_t a0 = stB + (uint32_t)(b1row * PB + b1colh) * 2;
            ldsm4(kbh[0], a0);
            ldsm4(kbl[0], a0 + 9216);
        }
        #pragma unroll
        for (int ks = 0; ks < 4; ks++) {
            if (ks + 1 < 4) {
                uint32_t a = stB + (uint32_t)(b1row * PB + (ks + 1) * 16 + b1colh) * 2;
                ldsm4(kbh[(ks + 1) & 1], a);
                ldsm4(kbl[(ks + 1) & 1], a + 9216);
            }
            const uint32_t* bh4 = kbh[ks & 1];
            const uint32_t* bl4 = kbl[ks & 1];
            mma_bf16(sacc[0], qa_h[ks], bh4[0], bh4[1]);
            mma_bf16(sacc[1], qa_h[ks], bh4[2], bh4[3]);
            mma_bf16(sacc[0], qa_h[ks], bl4[0], bl4[1]);
            mma_bf16(sacc[1], qa_h[ks], bl4[2], bl4[3]);
            mma_bf16(sacc[0], qa_l[ks], bh4[0], bh4[1]);
            mma_bf16(sacc[1], qa_l[ks], bh4[2], bh4[3]);
        }

        // preload V frags for dc=0 (independent of the epilogue below)
        uint32_t vbh[2][4], vbl[2][4];
        {
            uint32_t v0 = stB + 18432 + (uint32_t)(b2row * PB + b2colh) * 2;
            ldsm4t(vbh[0], v0);
            ldsm4t(vbl[0], v0 + 9216);
        }

        // ---- epilogue: exp+mask -> attn gmem (unnormalized) + A-frags ----
        const int j0 = jt * 64;
        uint32_t ah[4], al[4];
        #pragma unroll
        for (int nb = 0; nb < 2; nb++) {
            int lcol = wj * 16 + nb * 8 + 2 * t;
            int jj = j0 + lcol;
            float mj0 = mc[jj], mj1 = mc[jj + 1];
            float u0 = (mj0 == 0.0f) ? 1.0f : 0.0f;
            float u1 = (mj1 == 0.0f) ? 1.0f : 0.0f;
            float e00 = rowM0 ? u0 : __expf(fmaf(sacc[nb][0], 0.125f, -mj0));
            float e01 = rowM0 ? u1 : __expf(fmaf(sacc[nb][1], 0.125f, -mj1));
            float e10 = rowM1 ? u0 : __expf(fmaf(sacc[nb][2], 0.125f, -mj0));
            float e11 = rowM1 ? u1 : __expf(fmaf(sacc[nb][3], 0.125f, -mj1));
            rs0 += e00 + e01;
            rs1 += e10 + e11;
            if (ab) {
                *(float2*)&ab[(size_t)r0l * LEN + jj] = make_float2(e00, e01);
                *(float2*)&ab[(size_t)r1l * LEN + jj] = make_float2(e10, e11);
            }
            split2(e00, e01, ah[2 * nb],     al[2 * nb]);
            split2(e10, e11, ah[2 * nb + 1], al[2 * nb + 1]);
        }

        // ---- GEMM2: partial O(16x64) += E_slice(16x16) . V_slice(16x64) ----
        // Software-pipelined over dc.
        #pragma unroll
        for (int dc = 0; dc < 4; dc++) {
            if (dc + 1 < 4) {
                uint32_t va = stB + 18432 + (uint32_t)(b2row * PB + (dc + 1) * 16 + b2colh) * 2;
                ldsm4t(vbh[(dc + 1) & 1], va);
                ldsm4t(vbl[(dc + 1) & 1], va + 9216);
            }
            const uint32_t* vh4 = vbh[dc & 1];
            const uint32_t* vl4 = vbl[dc & 1];
            mma_bf16(oacc[2 * dc],     ah, vh4[0], vh4[1]);
            mma_bf16(oacc[2 * dc + 1], ah, vh4[2], vh4[3]);
            mma_bf16(oacc[2 * dc],     ah, vl4[0], vl4[1]);
            mma_bf16(oacc[2 * dc + 1], ah, vl4[2], vl4[3]);
            mma_bf16(oacc[2 * dc],     al, vh4[0], vh4[1]);
            mma_bf16(oacc[2 * dc + 1], al, vh4[2], vh4[3]);
        }

        CP_WAIT0();       // next tile's loads done (overlapped with compute)
        __syncthreads();  // all warps done with this stage
    }

    // ---- rowsum reduction ----
    rs0 += __shfl_xor_sync(0xffffffffu, rs0, 1);
    rs0 += __shfl_xor_sync(0xffffffffu, rs0, 2);
    rs1 += __shfl_xor_sync(0xffffffffu, rs1, 1);
    rs1 += __shfl_xor_sync(0xffffffffu, rs1, 2);
    if (t == 0) {
        rsp[r0l][wj] = rs0;
        rsp[r1l][wj] = rs1;
    }
    // dump partial O into the (now dead) stage-0 region
    #pragma unroll
    for (int nb = 0; nb < 8; nb++) {
        int col = nb * 8 + 2 * t;
        *(float2*)&Ob[wj * (32 * OBP) + r0l * OBP + col] = make_float2(oacc[nb][0], oacc[nb][1]);
        *(float2*)&Ob[wj * (32 * OBP) + r1l * OBP + col] = make_float2(oacc[nb][2], oacc[nb][3]);
    }
    __syncthreads();

    if (tid < TI)
        rinv[tid] = 1.0f / (rsp[tid][0] + rsp[tid][1] + rsp[tid][2] + rsp[tid][3]);
    __syncthreads();

    // ---- O reduce across 4 k-slices + write ----
    if (out_o) {
        int row = tid >> 3;
        int c8  = (tid & 7) * 8;
        float s[8];
        #pragma unroll
        for (int i = 0; i < 8; i++) s[i] = 0.0f;
        #pragma unroll
        for (int p = 0; p < 4; p++) {
            const float* src = &Ob[p * (32 * OBP) + row * OBP + c8];
            #pragma unroll
            for (int i = 0; i < 8; i++) s[i] += src[i];
        }
        float inv = rinv[row];
        float* ob = out_o + ((size_t)bh * LEN + i0 + row) * DIM + c8;
        *(float4*)ob       = make_float4(s[0] * inv, s[1] * inv, s[2] * inv, s[3] * inv);
        *(float4*)(ob + 4) = make_float4(s[4] * inv, s[5] * inv, s[6] * inv, s[7] * inv);
    }

    // ---- normalize attn in place (CTA just wrote it; L2-hot) ----
    if (ab) {
        #pragma unroll 4
        for (int i4 = tid; i4 < TI * (LEN / 4); i4 += NT) {
            int row = i4 >> 7;
            int col = (i4 & 127) * 4;
            float inv = rinv[row];
            float4 e = *(const float4*)&ab[(size_t)row * LEN + col];
            e.x *= inv; e.y *= inv; e.z *= inv; e.w *= inv;
            *(float4*)&ab[(size_t)row * LEN + col] = e;
        }
    }
}

extern "C" void kernel_launch(void* const* d_in, const int* in_sizes, int n_in,
                              void* d_out, int out_size)
{
    const float* q    = (const float*)d_in[0];
    const float* k    = (const float*)d_in[1];
    const float* v    = (const float*)d_in[2];
    const float* mask = (const float*)d_in[3];

    const long long O_ELEMS = (long long)BH * LEN * DIM;   // 4194304
    const long long A_ELEMS = (long long)BH * LEN * LEN;   // 33554432

    float* out = (float*)d_out;
    float* o_ptr = nullptr;
    float* a_ptr = nullptr;
    if ((long long)out_size >= O_ELEMS + A_ELEMS) {
        o_ptr = out;
        a_ptr = out + O_ELEMS;
    } else if ((long long)out_size == A_ELEMS) {
        a_ptr = out;
    } else {
        o_ptr = out;
    }

    dim3 sgrid(NELEM / 8 / 256, 2);
    split2_kernel<<<sgrid, 256>>>(k, v);

    cudaFuncSetAttribute(attn_tc_kernel,
                         cudaFuncAttributeMaxDynamicSharedMemorySize, SMEM_BYTES);

    dim3 grid(LEN / TI, BH);   // (16, 128) = 2048 CTAs
    attn_tc_kernel<<<grid, NT, SMEM_BYTES>>>(q, mask, o_ptr, a_ptr);
}

// round 10
// speedup vs baseline: 1.2063x; 1.1181x over previous
#include <cuda_runtime.h>
#include <cuda_bf16.h>
#include <cstdint>
#include <cstddef>

// Problem constants: B=16, H=8, L=512, D=64
#define BH   128
#define LEN  512
#define DIM  64
#define TI   64          // q-rows per CTA
#define NT   256         // 8 warps: 4 row-groups (wi) x 2 k-groups (wj)
#define NJT  8           // 512/64 j-tiles
#define PB   72          // bf16 smem pitch (144B rows)
#define NELEM (BH*LEN*DIM)

// smem layout (bytes)
// stage s (s=0,1) at s*STAGE_BYTES: KH +0, KL +9216, VH +18432, VL +27648
#define STAGE_BYTES 36864
#define OFF_Q   73728            // QH 9216 (64 x 72 bf16), QL at +9216
#define OFF_MC  92160            // 512 f32
#define OFF_RS  94208            // 64 x 2 f32
#define OFF_RI  94720            // 64 f32
#define SMEM_BYTES 94976
// O-reduction buffer reuses dead stage-0 after the loop: 2*64*66*4 = 33792 B
#define OBP 66

// pre-split bf16 hi/lo scratch for K and V (written by prologue kernel)
__device__ __nv_bfloat16 g_kh[NELEM];
__device__ __nv_bfloat16 g_kl[NELEM];
__device__ __nv_bfloat16 g_vh[NELEM];
__device__ __nv_bfloat16 g_vl[NELEM];

__device__ __forceinline__ uint32_t smem_u32(const void* p) {
    return (uint32_t)__cvta_generic_to_shared(p);
}
__device__ __forceinline__ void ldsm4(uint32_t* r, uint32_t a) {
    asm volatile("ldmatrix.sync.aligned.m8n8.x4.shared.b16 {%0,%1,%2,%3}, [%4];"
                 : "=r"(r[0]), "=r"(r[1]), "=r"(r[2]), "=r"(r[3]) : "r"(a));
}
__device__ __forceinline__ void ldsm4t(uint32_t* r, uint32_t a) {
    asm volatile("ldmatrix.sync.aligned.m8n8.x4.trans.shared.b16 {%0,%1,%2,%3}, [%4];"
                 : "=r"(r[0]), "=r"(r[1]), "=r"(r[2]), "=r"(r[3]) : "r"(a));
}
__device__ __forceinline__ void mma_bf16(float* c, const uint32_t* a, uint32_t b0, uint32_t b1) {
    asm volatile("mma.sync.aligned.m16n8k16.row.col.f32.bf16.bf16.f32 "
                 "{%0,%1,%2,%3}, {%4,%5,%6,%7}, {%8,%9}, {%0,%1,%2,%3};"
                 : "+f"(c[0]), "+f"(c[1]), "+f"(c[2]), "+f"(c[3])
                 : "r"(a[0]), "r"(a[1]), "r"(a[2]), "r"(a[3]), "r"(b0), "r"(b1));
}
__device__ __forceinline__ void split2(float x0, float x1, uint32_t& h, uint32_t& l) {
    __nv_bfloat16 h0 = __float2bfloat16(x0);
    __nv_bfloat16 h1 = __float2bfloat16(x1);
    __nv_bfloat16 l0 = __float2bfloat16(x0 - __bfloat162float(h0));
    __nv_bfloat16 l1 = __float2bfloat16(x1 - __bfloat162float(h1));
    __nv_bfloat162 hp = __nv_bfloat162(h0, h1);
    __nv_bfloat162 lp = __nv_bfloat162(l0, l1);
    h = *reinterpret_cast<uint32_t*>(&hp);
    l = *reinterpret_cast<uint32_t*>(&lp);
}
#define CP16(dst, src) \
    asm volatile("cp.async.cg.shared.global [%0], [%1], 16;" :: "r"(dst), "l"(src))
#define CP_COMMIT() asm volatile("cp.async.commit_group;")
#define CP_WAIT0()  asm volatile("cp.async.wait_group 0;")

// ---------------- prologue: fp32 -> bf16 hi/lo split (K and V) ----------------
__global__ void __launch_bounds__(256)
split2_kernel(const float* __restrict__ k,
              const float* __restrict__ v)
{
    const float* src = (blockIdx.y == 0) ? k : v;
    __nv_bfloat16* hi = (blockIdx.y == 0) ? g_kh : g_vh;
    __nv_bfloat16* lo = (blockIdx.y == 0) ? g_kl : g_vl;

    int i = blockIdx.x * 256 + threadIdx.x;       // 8-float chunk index
    float4 x0 = ((const float4*)src)[2 * i];
    float4 x1 = ((const float4*)src)[2 * i + 1];
    uint4 h, l;
    split2(x0.x, x0.y, h.x, l.x);
    split2(x0.z, x0.w, h.y, l.y);
    split2(x1.x, x1.y, h.z, l.z);
    split2(x1.z, x1.w, h.w, l.w);
    ((uint4*)hi)[i] = h;
    ((uint4*)lo)[i] = l;
}

// ---------------- main fused attention ----------------
__global__ void __launch_bounds__(NT, 2)
attn_tc_kernel(const float* __restrict__ q,
               const float* __restrict__ mask,
               float* __restrict__ out_o,
               float* __restrict__ out_attn)
{
    extern __shared__ char smc[];
    float* mc = (float*)(smc + OFF_MC);
    float (*rsp)[2] = (float (*)[2])(smc + OFF_RS);
    float* rinv = (float*)(smc + OFF_RI);
    float* Ob = (float*)smc;              // reuses stage 0 after the loop
    __nv_bfloat16* Qh = (__nv_bfloat16*)(smc + OFF_Q);
    __nv_bfloat16* Ql = (__nv_bfloat16*)(smc + OFF_Q + 9216);

    const int bh  = blockIdx.y;
    const int i0  = blockIdx.x * TI;
    const int b   = bh >> 3;              // H = 8
    const int tid = threadIdx.x;
    const int L   = tid & 31;
    const int w   = tid >> 5;             // warp 0..7
    const int wi  = w & 3;                // 16-row group
    const int wj  = w >> 2;               // 0..1 -> 32-col (=k) group
    const int g   = L >> 2;
    const int t   = L & 3;

    const uint32_t smB = smem_u32(smc);
    const uint32_t qhB = smB + OFF_Q;

    const __nv_bfloat16* kh_b = g_kh + (size_t)bh * LEN * DIM;
    const __nv_bfloat16* kl_b = g_kl + (size_t)bh * LEN * DIM;
    const __nv_bfloat16* vh_b = g_vh + (size_t)bh * LEN * DIM;
    const __nv_bfloat16* vl_b = g_vl + (size_t)bh * LEN * DIM;

    // per-thread cp.async addressing for K/V tiles
    const int cprow0 = tid >> 3;              // rows tid/8 and tid/8+32
    const int cpch   = (tid & 7) * 8;
    const uint32_t cpdoff0 = (uint32_t)(cprow0 * PB + cpch) * 2;
    const uint32_t cpdoff1 = (uint32_t)((cprow0 + 32) * PB + cpch) * 2;

    // issue tile 0 into stage 0 first (loads fly under Q split below)
    {
        int soff0 = cprow0 * DIM + cpch;
        int soff1 = (cprow0 + 32) * DIM + cpch;
        uint32_t s0 = smB;
        CP16(s0 + cpdoff0,          kh_b + soff0);
        CP16(s0 + cpdoff1,          kh_b + soff1);
        CP16(s0 + 9216  + cpdoff0,  kl_b + soff0);
        CP16(s0 + 9216  + cpdoff1,  kl_b + soff1);
        CP16(s0 + 18432 + cpdoff0,  vh_b + soff0);
        CP16(s0 + 18432 + cpdoff1,  vh_b + soff1);
        CP16(s0 + 27648 + cpdoff0,  vl_b + soff0);
        CP16(s0 + 27648 + cpdoff1,  vl_b + soff1);
        CP_COMMIT();
    }

    // column mask term: 0 or 1e9
    for (int j = tid; j < LEN; j += NT) {
        float mv = mask[b * LEN + j];
        mc[j] = (mv == -10000.0f) ? 1e9f : mv;
    }

    // inline Q split: 64x64 fp32 -> bf16 hi/lo in smem
    {
        const float* qb = q + ((size_t)bh * LEN + i0) * DIM;
        #pragma unroll
        for (int it = 0; it < 4; it++) {
            int lin = it * NT + tid;             // 0..1023 float4 chunks
            int row = lin >> 4;
            int c4  = (lin & 15) * 4;
            float4 x = *(const float4*)(qb + row * DIM + c4);
            uint32_t h01, l01, h23, l23;
            split2(x.x, x.y, h01, l01);
            split2(x.z, x.w, h23, l23);
            *(uint32_t*)&Qh[row * PB + c4]     = h01;
            *(uint32_t*)&Qh[row * PB + c4 + 2] = h23;
            *(uint32_t*)&Ql[row * PB + c4]     = l01;
            *(uint32_t*)&Ql[row * PB + c4 + 2] = l23;
        }
    }
    CP_WAIT0();
    __syncthreads();

    float oacc[8][4];
    #pragma unroll
    for (int n = 0; n < 8; n++)
        #pragma unroll
        for (int c = 0; c < 4; c++) oacc[n][c] = 0.0f;
    float rs0 = 0.0f, rs1 = 0.0f;

    const int r0l = wi * 16 + g;
    const int r1l = r0l + 8;

    // Q A-frag addressing (per-tile reload from smem)
    const int arow = wi * 16 + (L & 15);
    const int acol = (L >> 4) * 8;
    // GEMM1 B (K): row base within warp's 32-j group
    const int b1rowb = wj * 32 + ((L >> 4) & 1) * 8 + (L & 7);
    const int b1col  = ((L >> 3) & 1) * 8;
    // GEMM2 B (V, trans)
    const int b2rowb = wj * 32 + ((L >> 3) & 1) * 8 + (L & 7);
    const int b2colh = (L >> 4) * 8;

    const bool rowM0 = (mc[i0 + r0l] != 0.0f);
    const bool rowM1 = (mc[i0 + r1l] != 0.0f);

    float* ab = out_attn ? out_attn + ((size_t)bh * LEN + i0) * LEN : nullptr;

    for (int jt = 0; jt < NJT; jt++) {
        const uint32_t stB = smB + (uint32_t)(jt & 1) * STAGE_BYTES;

        // prefetch next tile into the other stage
        if (jt + 1 < NJT) {
            const int j1 = (jt + 1) * 64;
            uint32_t s1 = smB + (uint32_t)((jt + 1) & 1) * STAGE_BYTES;
            int soff0 = (j1 + cprow0) * DIM + cpch;
            int soff1 = (j1 + cprow0 + 32) * DIM + cpch;
            CP16(s1 + cpdoff0,          kh_b + soff0);
            CP16(s1 + cpdoff1,          kh_b + soff1);
            CP16(s1 + 9216  + cpdoff0,  kl_b + soff0);
            CP16(s1 + 9216  + cpdoff1,  kl_b + soff1);
            CP16(s1 + 18432 + cpdoff0,  vh_b + soff0);
            CP16(s1 + 18432 + cpdoff1,  vh_b + soff1);
            CP16(s1 + 27648 + cpdoff0,  vl_b + soff0);
            CP16(s1 + 27648 + cpdoff1,  vl_b + soff1);
            CP_COMMIT();
        }

        // ---- GEMM1: S(16x32 per warp) = Q.K^T, 3-pass bf16 split ----
        float sacc[4][4];
        #pragma unroll
        for (int n = 0; n < 4; n++)
            #pragma unroll
            for (int c = 0; c < 4; c++) sacc[n][c] = 0.0f;

        #pragma unroll
        for (int ks = 0; ks < 4; ks++) {
            uint32_t qaddr = qhB + (uint32_t)(arow * PB + ks * 16 + acol) * 2;
            uint32_t qh4[4], ql4[4];
            ldsm4(qh4, qaddr);
            ldsm4(ql4, qaddr + 9216);
            #pragma unroll
            for (int jb = 0; jb < 2; jb++) {
                uint32_t addr = stB + (uint32_t)((b1rowb + jb * 16) * PB + ks * 16 + b1col) * 2;
                uint32_t bh4[4], bl4[4];
                ldsm4(bh4, addr);
                ldsm4(bl4, addr + 9216);
                mma_bf16(sacc[2 * jb],     qh4, bh4[0], bh4[1]);
                mma_bf16(sacc[2 * jb + 1], qh4, bh4[2], bh4[3]);
                mma_bf16(sacc[2 * jb],     qh4, bl4[0], bl4[1]);
                mma_bf16(sacc[2 * jb + 1], qh4, bl4[2], bl4[3]);
                mma_bf16(sacc[2 * jb],     ql4, bh4[0], bh4[1]);
                mma_bf16(sacc[2 * jb + 1], ql4, bh4[2], bh4[3]);
            }
        }

        // ---- epilogue: exp+mask -> attn gmem (unnormalized) + A-frags ----
        const int j0 = jt * 64;
        uint32_t ah[8], al[8];
        #pragma unroll
        for (int nb = 0; nb < 4; nb++) {
            int lcol = wj * 32 + nb * 8 + 2 * t;
            int jj = j0 + lcol;
            float mj0 = mc[jj], mj1 = mc[jj + 1];
            float u0 = (mj0 == 0.0f) ? 1.0f : 0.0f;
            float u1 = (mj1 == 0.0f) ? 1.0f : 0.0f;
            float e00 = rowM0 ? u0 : __expf(fmaf(sacc[nb][0], 0.125f, -mj0));
            float e01 = rowM0 ? u1 : __expf(fmaf(sacc[nb][1], 0.125f, -mj1));
            float e10 = rowM1 ? u0 : __expf(fmaf(sacc[nb][2], 0.125f, -mj0));
            float e11 = rowM1 ? u1 : __expf(fmaf(sacc[nb][3], 0.125f, -mj1));
            rs0 += e00 + e01;
            rs1 += e10 + e11;
            if (ab) {
                *(float2*)&ab[(size_t)r0l * LEN + jj] = make_float2(e00, e01);
                *(float2*)&ab[(size_t)r1l * LEN + jj] = make_float2(e10, e11);
            }
            // A-frag packing: kb = nb>>1; slot = 4*kb + 2*(nb&1)
            int base = (nb >> 1) * 4 + (nb & 1) * 2;
            split2(e00, e01, ah[base],     al[base]);
            split2(e10, e11, ah[base + 1], al[base + 1]);
        }

        // ---- GEMM2: partial O(16x64) += E_slice(16x32) . V_slice(32x64) ----
        #pragma unroll
        for (int ks2 = 0; ks2 < 2; ks2++) {
            const uint32_t* a_h = ah + 4 * ks2;
            const uint32_t* a_l = al + 4 * ks2;
            #pragma unroll
            for (int dc = 0; dc < 4; dc++) {
                uint32_t vaddr = stB + 18432 +
                    (uint32_t)((b2rowb + ks2 * 16) * PB + dc * 16 + b2colh) * 2;
                uint32_t vh4[4], vl4[4];
                ldsm4t(vh4, vaddr);
                ldsm4t(vl4, vaddr + 9216);
                mma_bf16(oacc[2 * dc],     a_h, vh4[0], vh4[1]);
                mma_bf16(oacc[2 * dc + 1], a_h, vh4[2], vh4[3]);
                mma_bf16(oacc[2 * dc],     a_h, vl4[0], vl4[1]);
                mma_bf16(oacc[2 * dc + 1], a_h, vl4[2], vl4[3]);
                mma_bf16(oacc[2 * dc],     a_l, vh4[0], vh4[1]);
                mma_bf16(oacc[2 * dc + 1], a_l, vh4[2], vh4[3]);
            }
        }

        CP_WAIT0();       // next tile's loads done (overlapped with compute)
        __syncthreads();  // all warps done with this stage
    }

    // ---- rowsum reduction across t-lanes then across the 2 wj groups ----
    rs0 += __shfl_xor_sync(0xffffffffu, rs0, 1);
    rs0 += __shfl_xor_sync(0xffffffffu, rs0, 2);
    rs1 += __shfl_xor_sync(0xffffffffu, rs1, 1);
    rs1 += __shfl_xor_sync(0xffffffffu, rs1, 2);
    if (t == 0) {
        rsp[r0l][wj] = rs0;
        rsp[r1l][wj] = rs1;
    }
    // dump partial O into the (now dead) stage-0 region
    #pragma unroll
    for (int nb = 0; nb < 8; nb++) {
        int col = nb * 8 + 2 * t;
        *(float2*)&Ob[wj * (64 * OBP) + r0l * OBP + col] = make_float2(oacc[nb][0], oacc[nb][1]);
        *(float2*)&Ob[wj * (64 * OBP) + r1l * OBP + col] = make_float2(oacc[nb][2], oacc[nb][3]);
    }
    __syncthreads();

    if (tid < TI)
        rinv[tid] = 1.0f / (rsp[tid][0] + rsp[tid][1]);
    __syncthreads();

    // ---- O reduce across 2 k-slices + write ----
    if (out_o) {
        #pragma unroll
        for (int rr = 0; rr < 2; rr++) {
            int row = rr * 32 + (tid >> 3);
            int c8  = (tid & 7) * 8;
            float s[8];
            #pragma unroll
            for (int i = 0; i < 8; i++)
                s[i] = Ob[row * OBP + c8 + i] + Ob[64 * OBP + row * OBP + c8 + i];
            float inv = rinv[row];
            float* ob = out_o + ((size_t)bh * LEN + i0 + row) * DIM + c8;
            *(float4*)ob       = make_float4(s[0] * inv, s[1] * inv, s[2] * inv, s[3] * inv);
            *(float4*)(ob + 4) = make_float4(s[4] * inv, s[5] * inv, s[6] * inv, s[7] * inv);
        }
    }

    // ---- normalize attn in place (CTA just wrote it; L2-hot) ----
    if (ab) {
        #pragma unroll 4
        for (int i4 = tid; i4 < TI * (LEN / 4); i4 += NT) {
            int row = i4 >> 7;
            int col = (i4 & 127) * 4;
            float inv = rinv[row];
            float4 e = *(const float4*)&ab[(size_t)row * LEN + col];
            e.x *= inv; e.y *= inv; e.z *= inv; e.w *= inv;
            *(float4*)&ab[(size_t)row * LEN + col] = e;
        }
    }
}

extern "C" void kernel_launch(void* const* d_in, const int* in_sizes, int n_in,
                              void* d_out, int out_size)
{
    const float* q    = (const float*)d_in[0];
    const float* k    = (const float*)d_in[1];
    const float* v    = (const float*)d_in[2];
    const float* mask = (const float*)d_in[3];

    const long long O_ELEMS = (long long)BH * LEN * DIM;   // 4194304
    const long long A_ELEMS = (long long)BH * LEN * LEN;   // 33554432

    float* out = (float*)d_out;
    float* o_ptr = nullptr;
    float* a_ptr = nullptr;
    if ((long long)out_size >= O_ELEMS + A_ELEMS) {
        o_ptr = out;
        a_ptr = out + O_ELEMS;
    } else if ((long long)out_size == A_ELEMS) {
        a_ptr = out;
    } else {
        o_ptr = out;
    }

    dim3 sgrid(NELEM / 8 / 256, 2);
    split2_kernel<<<sgrid, 256>>>(k, v);

    cudaFuncSetAttribute(attn_tc_kernel,
                         cudaFuncAttributeMaxDynamicSharedMemorySize, SMEM_BYTES);

    dim3 grid(LEN / TI, BH);   // (8, 128) = 1024 CTAs
    attn_tc_kernel<<<grid, NT, SMEM_BYTES>>>(q, mask, o_ptr, a_ptr);
}